// round 7
// baseline (speedup 1.0000x reference)
#include <cuda_runtime.h>
#include <cuda_bf16.h>
#include <mma.h>
#include <cstdint>

#define B_SZ 2048
#define N_SZ 128
#define D_SZ 512
#define NT_F 128

using namespace nvcuda;

// scratch: cw = content @ cow (fp32), plus bf16 split cow
__device__ float g_cw[B_SZ * 2 * D_SZ];                      // 8 MB
__device__ __nv_bfloat16 g_b_hi[D_SZ * D_SZ];                // 0.5 MB (cow, [k][n])
__device__ __nv_bfloat16 g_b_lo[D_SZ * D_SZ];                // 0.5 MB

__device__ __forceinline__ float tanh_mufu(float x) {
    float y; asm("tanh.approx.f32 %0, %1;" : "=f"(y) : "f"(x)); return y;
}
__device__ __forceinline__ float tanh_precise(float x) {
    float ax = fabsf(x);
    if (ax > 15.0f) return copysignf(1.0f, x);
    float t = __expf(2.0f * x);
    return (t - 1.0f) / (t + 1.0f);
}
__device__ __forceinline__ float warp_sum(float v) {
    #pragma unroll
    for (int o = 16; o > 0; o >>= 1) v += __shfl_xor_sync(0xffffffffu, v, o);
    return v;
}

// ======================= prep: cow split =======================
// cow [k][n] row-major split to bf16 hi/lo (matches wmma matrix_b row_major)
__global__ void __launch_bounds__(256) prep_cow_kernel(const float* __restrict__ cow)
{
    int idx = blockIdx.x * 256 + threadIdx.x;      // float4 id, total 64K
    float4 v = ((const float4*)cow)[idx];
    float xs[4] = {v.x, v.y, v.z, v.w};
    __nv_bfloat16 hi[4], lo[4];
    #pragma unroll
    for (int i = 0; i < 4; i++) {
        hi[i] = __float2bfloat16(xs[i]);
        lo[i] = __float2bfloat16(xs[i] - __bfloat162float(hi[i]));
    }
    __nv_bfloat162* ph = (__nv_bfloat162*)g_b_hi;
    __nv_bfloat162* pl = (__nv_bfloat162*)g_b_lo;
    ph[idx * 2]     = __nv_bfloat162(hi[0], hi[1]);
    ph[idx * 2 + 1] = __nv_bfloat162(hi[2], hi[3]);
    pl[idx * 2]     = __nv_bfloat162(lo[0], lo[1]);
    pl[idx * 2 + 1] = __nv_bfloat162(lo[2], lo[3]);
}

// ======================= wmma bf16 split GEMM (A split fused in) ===========
// cw[4096 x 512] = A[4096 x 512] @ B[512 x 512]; 3 split terms.
// BM=64, BN=128, BK=32; 8 warps, each a 32x32 tile (2x2 wmma frags).
#define GA_LD 40
#define GB_LD 136
__global__ void __launch_bounds__(256) gemm_wmma_kernel(
    const float* __restrict__ text, const float* __restrict__ img)
{
    __shared__ __nv_bfloat16 sAhi[64][GA_LD];
    __shared__ __nv_bfloat16 sAlo[64][GA_LD];
    __shared__ __nv_bfloat16 sBhi[32][GB_LD];
    __shared__ __nv_bfloat16 sBlo[32][GB_LD];

    const int tid  = threadIdx.x;
    const int w    = tid >> 5;
    const int wm   = w >> 2;            // 0..1
    const int wn   = w & 3;             // 0..3
    const int row0 = blockIdx.y * 64;
    const int col0 = blockIdx.x * 128;

    wmma::fragment<wmma::accumulator, 16, 16, 16, float> acc[2][2];
    #pragma unroll
    for (int i = 0; i < 2; i++)
        #pragma unroll
        for (int j = 0; j < 2; j++) wmma::fill_fragment(acc[i][j], 0.0f);

    // A tile: 64x32 fp32, 8 floats (2 float4) per thread; split in-register.
    const int aRow = tid >> 2;
    const int aC8  = (tid & 3) * 8;
    const int grow = row0 + aRow;
    const float* srcA = (grow & 1) ? img : text;
    const float* aPtr = srcA + (size_t)(grow >> 1) * D_SZ + aC8;

    for (int kk = 0; kk < D_SZ; kk += 32) {
        float4 av0 = *(const float4*)(aPtr + kk);
        float4 av1 = *(const float4*)(aPtr + kk + 4);
        float xs[8] = {av0.x, av0.y, av0.z, av0.w, av1.x, av1.y, av1.z, av1.w};
        __nv_bfloat16 hi[8], lo[8];
        #pragma unroll
        for (int i = 0; i < 8; i++) {
            hi[i] = __float2bfloat16(xs[i]);
            lo[i] = __float2bfloat16(xs[i] - __bfloat162float(hi[i]));
        }
        *(uint4*)&sAhi[aRow][aC8] = *(const uint4*)hi;
        *(uint4*)&sAlo[aRow][aC8] = *(const uint4*)lo;

        #pragma unroll
        for (int it = 0; it < 2; it++) {
            int s    = tid + it * 256;
            int bRow = s >> 4;
            int bC8  = (s & 15) * 8;
            *(uint4*)&sBhi[bRow][bC8] =
                *(const uint4*)(g_b_hi + (size_t)(kk + bRow) * D_SZ + col0 + bC8);
            *(uint4*)&sBlo[bRow][bC8] =
                *(const uint4*)(g_b_lo + (size_t)(kk + bRow) * D_SZ + col0 + bC8);
        }
        __syncthreads();

        #pragma unroll
        for (int ks = 0; ks < 32; ks += 16) {
            wmma::fragment<wmma::matrix_a, 16, 16, 16, __nv_bfloat16, wmma::row_major> aH[2], aL[2];
            wmma::fragment<wmma::matrix_b, 16, 16, 16, __nv_bfloat16, wmma::row_major> bH[2], bL[2];
            #pragma unroll
            for (int i = 0; i < 2; i++) {
                wmma::load_matrix_sync(aH[i], &sAhi[wm * 32 + i * 16][ks], GA_LD);
                wmma::load_matrix_sync(aL[i], &sAlo[wm * 32 + i * 16][ks], GA_LD);
            }
            #pragma unroll
            for (int j = 0; j < 2; j++) {
                wmma::load_matrix_sync(bH[j], &sBhi[ks][wn * 32 + j * 16], GB_LD);
                wmma::load_matrix_sync(bL[j], &sBlo[ks][wn * 32 + j * 16], GB_LD);
            }
            #pragma unroll
            for (int i = 0; i < 2; i++)
                #pragma unroll
                for (int j = 0; j < 2; j++) {
                    wmma::mma_sync(acc[i][j], aH[i], bH[j], acc[i][j]);
                    wmma::mma_sync(acc[i][j], aH[i], bL[j], acc[i][j]);
                    wmma::mma_sync(acc[i][j], aL[i], bH[j], acc[i][j]);
                }
        }
        __syncthreads();
    }

    #pragma unroll
    for (int i = 0; i < 2; i++)
        #pragma unroll
        for (int j = 0; j < 2; j++)
            wmma::store_matrix_sync(
                g_cw + (size_t)(row0 + wm * 32 + i * 16) * D_SZ + col0 + wn * 32 + j * 16,
                acc[i][j], D_SZ, wmma::mem_row_major);
}

// ======================= fused kernel v4: single row/warp-iter =============
__global__ void __launch_bounds__(NT_F, 5) fused_kernel(
    const float* __restrict__ text, const float* __restrict__ img,
    const float* __restrict__ comment, const int* __restrict__ comment_num,
    const float* __restrict__ W_ca, const float* __restrict__ b_ca,
    const float* __restrict__ W_co, const float* __restrict__ b_co,
    float* __restrict__ out)
{
    __shared__ float cwS[2 * D_SZ];
    __shared__ float ccS[2 * D_SZ];
    __shared__ float wcoS[D_SZ];
    __shared__ float wcaS[D_SZ];
    __shared__ float redS[3 * 4 * D_SZ];
    __shared__ float ssumS[4];
    __shared__ float pS[8];

    const int b    = blockIdx.x;
    const int tid  = threadIdx.x;
    const int lane = tid & 31;
    const int w    = tid >> 5;
    const int M    = comment_num[b];

    for (int i = tid; i < 2 * D_SZ / 4; i += NT_F)
        ((float4*)cwS)[i] = ((const float4*)(g_cw + (size_t)b * 2 * D_SZ))[i];
    for (int i = tid; i < D_SZ / 4; i += NT_F) {
        ((float4*)ccS)[i]          = ((const float4*)(text + (size_t)b * D_SZ))[i];
        ((float4*)(ccS + D_SZ))[i] = ((const float4*)(img  + (size_t)b * D_SZ))[i];
        ((float4*)wcoS)[i]         = ((const float4*)W_co)[i];
        ((float4*)wcaS)[i]         = ((const float4*)W_ca)[i];
    }
    __syncthreads();

    const float bco = b_co[0];

    const float4* cw04 = (const float4*)cwS;
    const float4* cw14 = (const float4*)(cwS + D_SZ);
    const float4* c04  = (const float4*)ccS;
    const float4* c14  = (const float4*)(ccS + D_SZ);
    const float4* wco4 = (const float4*)wcoS;

    float4 acc[4], s0[4], s1[4];
    #pragma unroll
    for (int j = 0; j < 4; j++) {
        acc[j] = make_float4(0.f, 0.f, 0.f, 0.f);
        s0[j]  = make_float4(0.f, 0.f, 0.f, 0.f);
        s1[j]  = make_float4(0.f, 0.f, 0.f, 0.f);
    }
    float ssum = 0.f;

    for (int n = w; n < M; n += 4) {
        const float4* zp = (const float4*)(comment + ((size_t)b * N_SZ + n) * D_SZ);
        float4 z[4];
        #pragma unroll
        for (int j = 0; j < 4; j++) z[j] = zp[lane + 32 * j];

        // --- co_w dots: a_k = cw_k . z ---
        float a0 = 0.f, a1 = 0.f;
        #pragma unroll
        for (int j = 0; j < 4; j++) {
            float4 ca = cw04[lane + 32 * j];
            float4 cb = cw14[lane + 32 * j];
            a0 = fmaf(z[j].x, ca.x, fmaf(z[j].y, ca.y, fmaf(z[j].z, ca.z, fmaf(z[j].w, ca.w, a0))));
            a1 = fmaf(z[j].x, cb.x, fmaf(z[j].y, cb.y, fmaf(z[j].z, cb.z, fmaf(z[j].w, cb.w, a1))));
        }
        a0 = warp_sum(a0);
        a1 = warp_sum(a1);
        const float w0 = tanh_precise(a0);   // co_w[0][n]
        const float w1 = tanh_precise(a1);   // co_w[1][n]

        // --- zw logit: l = sum_d tanh(z + w0*c0 + w1*c1) * W_co ---
        float l = 0.f;
        #pragma unroll
        for (int j = 0; j < 4; j++) {
            float4 u0 = c04[lane + 32 * j];
            float4 u1 = c14[lane + 32 * j];
            float4 wv = wco4[lane + 32 * j];
            l = fmaf(tanh_mufu(fmaf(w0, u0.x, fmaf(w1, u1.x, z[j].x))), wv.x, l);
            l = fmaf(tanh_mufu(fmaf(w0, u0.y, fmaf(w1, u1.y, z[j].y))), wv.y, l);
            l = fmaf(tanh_mufu(fmaf(w0, u0.z, fmaf(w1, u1.z, z[j].z))), wv.z, l);
            l = fmaf(tanh_mufu(fmaf(w0, u0.w, fmaf(w1, u1.w, z[j].w))), wv.w, l);
        }
        l = warp_sum(l);

        // logits bounded by sum|W_co| (~18): exp without max-shift is safe
        const float e = __expf(l + bco);
        ssum += e;

        // --- accumulate softmax numerator and s_k vectors ---
        #pragma unroll
        for (int j = 0; j < 4; j++) {
            acc[j].x = fmaf(e, z[j].x, acc[j].x);
            acc[j].y = fmaf(e, z[j].y, acc[j].y);
            acc[j].z = fmaf(e, z[j].z, acc[j].z);
            acc[j].w = fmaf(e, z[j].w, acc[j].w);
            s0[j].x  = fmaf(w0, z[j].x, s0[j].x);
            s0[j].y  = fmaf(w0, z[j].y, s0[j].y);
            s0[j].z  = fmaf(w0, z[j].z, s0[j].z);
            s0[j].w  = fmaf(w0, z[j].w, s0[j].w);
            s1[j].x  = fmaf(w1, z[j].x, s1[j].x);
            s1[j].y  = fmaf(w1, z[j].y, s1[j].y);
            s1[j].z  = fmaf(w1, z[j].z, s1[j].z);
            s1[j].w  = fmaf(w1, z[j].w, s1[j].w);
        }
    }

    // --- cross-warp merge ---
    #pragma unroll
    for (int j = 0; j < 4; j++) {
        const int idx = w * 128 + lane + 32 * j;
        ((float4*)redS)[idx]        = acc[j];
        ((float4*)redS)[512 + idx]  = s0[j];
        ((float4*)redS)[1024 + idx] = s1[j];
    }
    if (lane == 0) ssumS[w] = ssum;
    __syncthreads();

    float4 A  = make_float4(0.f, 0.f, 0.f, 0.f);
    float4 S0 = make_float4(0.f, 0.f, 0.f, 0.f);
    float4 S1 = make_float4(0.f, 0.f, 0.f, 0.f);
    #pragma unroll
    for (int ww = 0; ww < 4; ww++) {
        float4 a = ((float4*)redS)[ww * 128 + tid];
        float4 x = ((float4*)redS)[512 + ww * 128 + tid];
        float4 y = ((float4*)redS)[1024 + ww * 128 + tid];
        A.x += a.x; A.y += a.y; A.z += a.z; A.w += a.w;
        S0.x += x.x; S0.y += x.y; S0.z += x.z; S0.w += x.w;
        S1.x += y.x; S1.y += y.y; S1.z += y.z; S1.w += y.w;
    }
    const float stot = ssumS[0] + ssumS[1] + ssumS[2] + ssumS[3];
    const float inv = 1.0f / stot;

    float* out_rcontent = out;
    float* out_rcomment = out + (size_t)B_SZ * D_SZ;
    float* out_contentw = out + (size_t)2 * B_SZ * D_SZ;

    ((float4*)out_rcomment)[(size_t)b * 128 + tid] =
        make_float4(A.x * inv, A.y * inv, A.z * inv, A.w * inv);

    float4 c0q = c04[tid], c1q = c14[tid], waq = ((const float4*)wcaS)[tid];
    float p0 = tanh_mufu(c0q.x + S0.x) * waq.x + tanh_mufu(c0q.y + S0.y) * waq.y
             + tanh_mufu(c0q.z + S0.z) * waq.z + tanh_mufu(c0q.w + S0.w) * waq.w;
    float p1 = tanh_mufu(c1q.x + S1.x) * waq.x + tanh_mufu(c1q.y + S1.y) * waq.y
             + tanh_mufu(c1q.z + S1.z) * waq.z + tanh_mufu(c1q.w + S1.w) * waq.w;
    p0 = warp_sum(p0);
    p1 = warp_sum(p1);
    if (lane == 0) { pS[w] = p0; pS[4 + w] = p1; }
    __syncthreads();
    const float bca = b_ca[0];
    const float l0 = pS[0] + pS[1] + pS[2] + pS[3] + bca;
    const float l1 = pS[4] + pS[5] + pS[6] + pS[7] + bca;

    const float mx = fmaxf(l0, l1);
    const float e0 = __expf(l0 - mx), e1 = __expf(l1 - mx);
    const float is = 1.0f / (e0 + e1);
    const float q0 = e0 * is, q1 = e1 * is;

    if (tid == 0) {
        out_contentw[(size_t)b * 2 + 0] = q0;
        out_contentw[(size_t)b * 2 + 1] = q1;
    }
    ((float4*)out_rcontent)[(size_t)b * 128 + tid] =
        make_float4(c0q.x * q0 + c1q.x * q1, c0q.y * q0 + c1q.y * q1,
                    c0q.z * q0 + c1q.z * q1, c0q.w * q0 + c1q.w * q1);
}

// ---------------------------------------------------------------------------
extern "C" void kernel_launch(void* const* d_in, const int* in_sizes, int n_in,
                              void* d_out, int out_size)
{
    const float* text        = (const float*)d_in[0];
    const float* img         = (const float*)d_in[1];
    const float* comment     = (const float*)d_in[2];
    const int*   comment_num = (const int*)  d_in[3];
    const float* cow         = (const float*)d_in[4];
    const float* W_ca        = (const float*)d_in[5];
    const float* b_ca        = (const float*)d_in[6];
    const float* W_co        = (const float*)d_in[7];
    const float* b_co        = (const float*)d_in[8];
    float* out = (float*)d_out;

    prep_cow_kernel<<<256, 256>>>(cow);

    dim3 gG(D_SZ / 128, (B_SZ * 2) / 64);   // (4, 64)
    gemm_wmma_kernel<<<gG, 256>>>(text, img);

    fused_kernel<<<B_SZ, NT_F>>>(text, img, comment, comment_num,
                                 W_ca, b_ca, W_co, b_co, out);
}

// round 8
// speedup vs baseline: 1.1031x; 1.1031x over previous
#include <cuda_runtime.h>
#include <cuda_bf16.h>
#include <mma.h>
#include <cstdint>

#define B_SZ 2048
#define N_SZ 128
#define D_SZ 512
#define NT_F 128
#define GRID_F 592     // 4 CTAs/SM * 148 SMs, persistent

using namespace nvcuda;

// scratch: cw = content @ cow (fp32), plus bf16 split cow
__device__ float g_cw[B_SZ * 2 * D_SZ];                      // 8 MB
__device__ __nv_bfloat16 g_b_hi[D_SZ * D_SZ];                // 0.5 MB (cow, [k][n])
__device__ __nv_bfloat16 g_b_lo[D_SZ * D_SZ];                // 0.5 MB
__device__ int g_ctr;                                        // work-steal counter

__device__ __forceinline__ float tanh_mufu(float x) {
    float y; asm("tanh.approx.f32 %0, %1;" : "=f"(y) : "f"(x)); return y;
}
__device__ __forceinline__ float tanh_precise(float x) {
    float ax = fabsf(x);
    if (ax > 15.0f) return copysignf(1.0f, x);
    float t = __expf(2.0f * x);
    return (t - 1.0f) / (t + 1.0f);
}
__device__ __forceinline__ float warp_sum(float v) {
    #pragma unroll
    for (int o = 16; o > 0; o >>= 1) v += __shfl_xor_sync(0xffffffffu, v, o);
    return v;
}

// ======================= prep: cow split (+ counter reset) =================
__global__ void __launch_bounds__(256) prep_cow_kernel(const float* __restrict__ cow)
{
    if (blockIdx.x == 0 && threadIdx.x == 0) g_ctr = GRID_F;
    int idx = blockIdx.x * 256 + threadIdx.x;      // float4 id, total 64K
    float4 v = ((const float4*)cow)[idx];
    float xs[4] = {v.x, v.y, v.z, v.w};
    __nv_bfloat16 hi[4], lo[4];
    #pragma unroll
    for (int i = 0; i < 4; i++) {
        hi[i] = __float2bfloat16(xs[i]);
        lo[i] = __float2bfloat16(xs[i] - __bfloat162float(hi[i]));
    }
    __nv_bfloat162* ph = (__nv_bfloat162*)g_b_hi;
    __nv_bfloat162* pl = (__nv_bfloat162*)g_b_lo;
    ph[idx * 2]     = __nv_bfloat162(hi[0], hi[1]);
    ph[idx * 2 + 1] = __nv_bfloat162(hi[2], hi[3]);
    pl[idx * 2]     = __nv_bfloat162(lo[0], lo[1]);
    pl[idx * 2 + 1] = __nv_bfloat162(lo[2], lo[3]);
}

// ======================= wmma bf16 split GEMM (A split fused in) ===========
#define GA_LD 40
#define GB_LD 136
__global__ void __launch_bounds__(256) gemm_wmma_kernel(
    const float* __restrict__ text, const float* __restrict__ img)
{
    __shared__ __nv_bfloat16 sAhi[64][GA_LD];
    __shared__ __nv_bfloat16 sAlo[64][GA_LD];
    __shared__ __nv_bfloat16 sBhi[32][GB_LD];
    __shared__ __nv_bfloat16 sBlo[32][GB_LD];

    const int tid  = threadIdx.x;
    const int w    = tid >> 5;
    const int wm   = w >> 2;
    const int wn   = w & 3;
    const int row0 = blockIdx.y * 64;
    const int col0 = blockIdx.x * 128;

    wmma::fragment<wmma::accumulator, 16, 16, 16, float> acc[2][2];
    #pragma unroll
    for (int i = 0; i < 2; i++)
        #pragma unroll
        for (int j = 0; j < 2; j++) wmma::fill_fragment(acc[i][j], 0.0f);

    const int aRow = tid >> 2;
    const int aC8  = (tid & 3) * 8;
    const int grow = row0 + aRow;
    const float* srcA = (grow & 1) ? img : text;
    const float* aPtr = srcA + (size_t)(grow >> 1) * D_SZ + aC8;

    for (int kk = 0; kk < D_SZ; kk += 32) {
        float4 av0 = *(const float4*)(aPtr + kk);
        float4 av1 = *(const float4*)(aPtr + kk + 4);
        float xs[8] = {av0.x, av0.y, av0.z, av0.w, av1.x, av1.y, av1.z, av1.w};
        __nv_bfloat16 hi[8], lo[8];
        #pragma unroll
        for (int i = 0; i < 8; i++) {
            hi[i] = __float2bfloat16(xs[i]);
            lo[i] = __float2bfloat16(xs[i] - __bfloat162float(hi[i]));
        }
        *(uint4*)&sAhi[aRow][aC8] = *(const uint4*)hi;
        *(uint4*)&sAlo[aRow][aC8] = *(const uint4*)lo;

        #pragma unroll
        for (int it = 0; it < 2; it++) {
            int s    = tid + it * 256;
            int bRow = s >> 4;
            int bC8  = (s & 15) * 8;
            *(uint4*)&sBhi[bRow][bC8] =
                *(const uint4*)(g_b_hi + (size_t)(kk + bRow) * D_SZ + col0 + bC8);
            *(uint4*)&sBlo[bRow][bC8] =
                *(const uint4*)(g_b_lo + (size_t)(kk + bRow) * D_SZ + col0 + bC8);
        }
        __syncthreads();

        #pragma unroll
        for (int ks = 0; ks < 32; ks += 16) {
            wmma::fragment<wmma::matrix_a, 16, 16, 16, __nv_bfloat16, wmma::row_major> aH[2], aL[2];
            wmma::fragment<wmma::matrix_b, 16, 16, 16, __nv_bfloat16, wmma::row_major> bH[2], bL[2];
            #pragma unroll
            for (int i = 0; i < 2; i++) {
                wmma::load_matrix_sync(aH[i], &sAhi[wm * 32 + i * 16][ks], GA_LD);
                wmma::load_matrix_sync(aL[i], &sAlo[wm * 32 + i * 16][ks], GA_LD);
            }
            #pragma unroll
            for (int j = 0; j < 2; j++) {
                wmma::load_matrix_sync(bH[j], &sBhi[ks][wn * 32 + j * 16], GB_LD);
                wmma::load_matrix_sync(bL[j], &sBlo[ks][wn * 32 + j * 16], GB_LD);
            }
            #pragma unroll
            for (int i = 0; i < 2; i++)
                #pragma unroll
                for (int j = 0; j < 2; j++) {
                    wmma::mma_sync(acc[i][j], aH[i], bH[j], acc[i][j]);
                    wmma::mma_sync(acc[i][j], aH[i], bL[j], acc[i][j]);
                    wmma::mma_sync(acc[i][j], aL[i], bH[j], acc[i][j]);
                }
        }
        __syncthreads();
    }

    #pragma unroll
    for (int i = 0; i < 2; i++)
        #pragma unroll
        for (int j = 0; j < 2; j++)
            wmma::store_matrix_sync(
                g_cw + (size_t)(row0 + wm * 32 + i * 16) * D_SZ + col0 + wn * 32 + j * 16,
                acc[i][j], D_SZ, wmma::mem_row_major);
}

// ======================= fused kernel: R6 pair body + persistent CTAs ======
__global__ void __launch_bounds__(NT_F, 4) fused_kernel(
    const float* __restrict__ text, const float* __restrict__ img,
    const float* __restrict__ comment, const int* __restrict__ comment_num,
    const float* __restrict__ W_ca, const float* __restrict__ b_ca,
    const float* __restrict__ W_co, const float* __restrict__ b_co,
    float* __restrict__ out)
{
    __shared__ float cwS[2 * D_SZ];
    __shared__ float ccS[2 * D_SZ];
    __shared__ float wcoS[D_SZ];
    __shared__ float wcaS[D_SZ];
    __shared__ float redS[3 * 4 * D_SZ];
    __shared__ float ssumS[4];
    __shared__ float pS[8];
    __shared__ int bS;

    const int tid  = threadIdx.x;
    const int lane = tid & 31;
    const int w    = tid >> 5;

    const float4* cw04 = (const float4*)cwS;
    const float4* cw14 = (const float4*)(cwS + D_SZ);
    const float4* c04  = (const float4*)ccS;
    const float4* c14  = (const float4*)(ccS + D_SZ);
    const float4* wco4 = (const float4*)wcoS;

    float* out_rcontent = out;
    float* out_rcomment = out + (size_t)B_SZ * D_SZ;
    float* out_contentw = out + (size_t)2 * B_SZ * D_SZ;

    int b = blockIdx.x;
    while (b < B_SZ) {
        const int M = comment_num[b];

        for (int i = tid; i < 2 * D_SZ / 4; i += NT_F)
            ((float4*)cwS)[i] = ((const float4*)(g_cw + (size_t)b * 2 * D_SZ))[i];
        for (int i = tid; i < D_SZ / 4; i += NT_F) {
            ((float4*)ccS)[i]          = ((const float4*)(text + (size_t)b * D_SZ))[i];
            ((float4*)(ccS + D_SZ))[i] = ((const float4*)(img  + (size_t)b * D_SZ))[i];
            ((float4*)wcoS)[i]         = ((const float4*)W_co)[i];
            ((float4*)wcaS)[i]         = ((const float4*)W_ca)[i];
        }
        __syncthreads();

        const float bco = b_co[0];

        float4 acc[4], s0[4], s1[4];
        #pragma unroll
        for (int j = 0; j < 4; j++) {
            acc[j] = make_float4(0.f, 0.f, 0.f, 0.f);
            s0[j]  = make_float4(0.f, 0.f, 0.f, 0.f);
            s1[j]  = make_float4(0.f, 0.f, 0.f, 0.f);
        }
        float ssum = 0.f;

        const int npairs = (M + 1) >> 1;
        for (int p = w; p < npairs; p += 4) {
            const int n0 = 2 * p;
            const bool v1 = (n0 + 1) < M;
            const float4* z0p = (const float4*)(comment + ((size_t)b * N_SZ + n0) * D_SZ);
            const float4* z1p = z0p + D_SZ / 4;

            float4 z0[4], z1[4];
            #pragma unroll
            for (int j = 0; j < 4; j++) z0[j] = z0p[lane + 32 * j];
            if (v1) {
                #pragma unroll
                for (int j = 0; j < 4; j++) z1[j] = z1p[lane + 32 * j];
            } else {
                #pragma unroll
                for (int j = 0; j < 4; j++) z1[j] = make_float4(0.f, 0.f, 0.f, 0.f);
            }

            float a00 = 0.f, a01 = 0.f, a10 = 0.f, a11 = 0.f;
            #pragma unroll
            for (int j = 0; j < 4; j++) {
                float4 ca = cw04[lane + 32 * j];
                float4 cb = cw14[lane + 32 * j];
                a00 = fmaf(z0[j].x, ca.x, fmaf(z0[j].y, ca.y, fmaf(z0[j].z, ca.z, fmaf(z0[j].w, ca.w, a00))));
                a01 = fmaf(z0[j].x, cb.x, fmaf(z0[j].y, cb.y, fmaf(z0[j].z, cb.z, fmaf(z0[j].w, cb.w, a01))));
                a10 = fmaf(z1[j].x, ca.x, fmaf(z1[j].y, ca.y, fmaf(z1[j].z, ca.z, fmaf(z1[j].w, ca.w, a10))));
                a11 = fmaf(z1[j].x, cb.x, fmaf(z1[j].y, cb.y, fmaf(z1[j].z, cb.z, fmaf(z1[j].w, cb.w, a11))));
            }
            a00 = warp_sum(a00); a01 = warp_sum(a01);
            a10 = warp_sum(a10); a11 = warp_sum(a11);
            const float w00 = tanh_precise(a00);
            const float w01 = tanh_precise(a01);
            const float w10 = tanh_precise(a10);
            const float w11 = tanh_precise(a11);

            float l0 = 0.f, l1 = 0.f;
            #pragma unroll
            for (int j = 0; j < 4; j++) {
                float4 u0 = c04[lane + 32 * j];
                float4 u1 = c14[lane + 32 * j];
                float4 wv = wco4[lane + 32 * j];
                l0 = fmaf(tanh_mufu(fmaf(w00, u0.x, fmaf(w01, u1.x, z0[j].x))), wv.x, l0);
                l0 = fmaf(tanh_mufu(fmaf(w00, u0.y, fmaf(w01, u1.y, z0[j].y))), wv.y, l0);
                l0 = fmaf(tanh_mufu(fmaf(w00, u0.z, fmaf(w01, u1.z, z0[j].z))), wv.z, l0);
                l0 = fmaf(tanh_mufu(fmaf(w00, u0.w, fmaf(w01, u1.w, z0[j].w))), wv.w, l0);
                l1 = fmaf(tanh_mufu(fmaf(w10, u0.x, fmaf(w11, u1.x, z1[j].x))), wv.x, l1);
                l1 = fmaf(tanh_mufu(fmaf(w10, u0.y, fmaf(w11, u1.y, z1[j].y))), wv.y, l1);
                l1 = fmaf(tanh_mufu(fmaf(w10, u0.z, fmaf(w11, u1.z, z1[j].z))), wv.z, l1);
                l1 = fmaf(tanh_mufu(fmaf(w10, u0.w, fmaf(w11, u1.w, z1[j].w))), wv.w, l1);
            }
            l0 = warp_sum(l0);
            l1 = warp_sum(l1);

            const float e0 = __expf(l0 + bco);
            const float e1 = v1 ? __expf(l1 + bco) : 0.f;
            ssum += e0 + e1;

            #pragma unroll
            for (int j = 0; j < 4; j++) {
                acc[j].x = fmaf(e0, z0[j].x, fmaf(e1, z1[j].x, acc[j].x));
                acc[j].y = fmaf(e0, z0[j].y, fmaf(e1, z1[j].y, acc[j].y));
                acc[j].z = fmaf(e0, z0[j].z, fmaf(e1, z1[j].z, acc[j].z));
                acc[j].w = fmaf(e0, z0[j].w, fmaf(e1, z1[j].w, acc[j].w));
                s0[j].x  = fmaf(w00, z0[j].x, fmaf(w10, z1[j].x, s0[j].x));
                s0[j].y  = fmaf(w00, z0[j].y, fmaf(w10, z1[j].y, s0[j].y));
                s0[j].z  = fmaf(w00, z0[j].z, fmaf(w10, z1[j].z, s0[j].z));
                s0[j].w  = fmaf(w00, z0[j].w, fmaf(w10, z1[j].w, s0[j].w));
                s1[j].x  = fmaf(w01, z0[j].x, fmaf(w11, z1[j].x, s1[j].x));
                s1[j].y  = fmaf(w01, z0[j].y, fmaf(w11, z1[j].y, s1[j].y));
                s1[j].z  = fmaf(w01, z0[j].z, fmaf(w11, z1[j].z, s1[j].z));
                s1[j].w  = fmaf(w01, z0[j].w, fmaf(w11, z1[j].w, s1[j].w));
            }
        }

        #pragma unroll
        for (int j = 0; j < 4; j++) {
            const int idx = w * 128 + lane + 32 * j;
            ((float4*)redS)[idx]        = acc[j];
            ((float4*)redS)[512 + idx]  = s0[j];
            ((float4*)redS)[1024 + idx] = s1[j];
        }
        if (lane == 0) ssumS[w] = ssum;
        __syncthreads();

        float4 A  = make_float4(0.f, 0.f, 0.f, 0.f);
        float4 S0 = make_float4(0.f, 0.f, 0.f, 0.f);
        float4 S1 = make_float4(0.f, 0.f, 0.f, 0.f);
        #pragma unroll
        for (int ww = 0; ww < 4; ww++) {
            float4 a = ((float4*)redS)[ww * 128 + tid];
            float4 x = ((float4*)redS)[512 + ww * 128 + tid];
            float4 y = ((float4*)redS)[1024 + ww * 128 + tid];
            A.x += a.x; A.y += a.y; A.z += a.z; A.w += a.w;
            S0.x += x.x; S0.y += x.y; S0.z += x.z; S0.w += x.w;
            S1.x += y.x; S1.y += y.y; S1.z += y.z; S1.w += y.w;
        }
        const float stot = ssumS[0] + ssumS[1] + ssumS[2] + ssumS[3];
        const float inv = 1.0f / stot;

        ((float4*)out_rcomment)[(size_t)b * 128 + tid] =
            make_float4(A.x * inv, A.y * inv, A.z * inv, A.w * inv);

        float4 c0q = c04[tid], c1q = c14[tid], waq = ((const float4*)wcaS)[tid];
        float p0 = tanh_mufu(c0q.x + S0.x) * waq.x + tanh_mufu(c0q.y + S0.y) * waq.y
                 + tanh_mufu(c0q.z + S0.z) * waq.z + tanh_mufu(c0q.w + S0.w) * waq.w;
        float p1 = tanh_mufu(c1q.x + S1.x) * waq.x + tanh_mufu(c1q.y + S1.y) * waq.y
                 + tanh_mufu(c1q.z + S1.z) * waq.z + tanh_mufu(c1q.w + S1.w) * waq.w;
        p0 = warp_sum(p0);
        p1 = warp_sum(p1);
        if (lane == 0) { pS[w] = p0; pS[4 + w] = p1; }
        __syncthreads();
        const float bca = b_ca[0];
        const float l0 = pS[0] + pS[1] + pS[2] + pS[3] + bca;
        const float l1 = pS[4] + pS[5] + pS[6] + pS[7] + bca;

        const float mx = fmaxf(l0, l1);
        const float e0 = __expf(l0 - mx), e1 = __expf(l1 - mx);
        const float is = 1.0f / (e0 + e1);
        const float q0 = e0 * is, q1 = e1 * is;

        if (tid == 0) {
            out_contentw[(size_t)b * 2 + 0] = q0;
            out_contentw[(size_t)b * 2 + 1] = q1;
        }
        ((float4*)out_rcontent)[(size_t)b * 128 + tid] =
            make_float4(c0q.x * q0 + c1q.x * q1, c0q.y * q0 + c1q.y * q1,
                        c0q.z * q0 + c1q.z * q1, c0q.w * q0 + c1q.w * q1);

        // --- fetch next work item (also fences smem reuse) ---
        __syncthreads();
        if (tid == 0) bS = atomicAdd(&g_ctr, 1);
        __syncthreads();
        b = bS;
    }
}

// ---------------------------------------------------------------------------
extern "C" void kernel_launch(void* const* d_in, const int* in_sizes, int n_in,
                              void* d_out, int out_size)
{
    const float* text        = (const float*)d_in[0];
    const float* img         = (const float*)d_in[1];
    const float* comment     = (const float*)d_in[2];
    const int*   comment_num = (const int*)  d_in[3];
    const float* cow         = (const float*)d_in[4];
    const float* W_ca        = (const float*)d_in[5];
    const float* b_ca        = (const float*)d_in[6];
    const float* W_co        = (const float*)d_in[7];
    const float* b_co        = (const float*)d_in[8];
    float* out = (float*)d_out;

    prep_cow_kernel<<<256, 256>>>(cow);

    dim3 gG(D_SZ / 128, (B_SZ * 2) / 64);   // (4, 64)
    gemm_wmma_kernel<<<gG, 256>>>(text, img);

    fused_kernel<<<GRID_F, NT_F>>>(text, img, comment, comment_num,
                                   W_ca, b_ca, W_co, b_co, out);
}